// round 1
// baseline (speedup 1.0000x reference)
#include <cuda_runtime.h>

typedef unsigned long long u64;
#define FULL 0xFFFFFFFFu

// ---- packed f32x2 helpers (Blackwell sm_100+) ----
__device__ __forceinline__ u64 pk2(float x, float y){
    u64 r; asm("mov.b64 %0,{%1,%2};" : "=l"(r) : "f"(x), "f"(y)); return r;
}
__device__ __forceinline__ float2 upk2(u64 a){
    float2 r; asm("mov.b64 {%0,%1},%2;" : "=f"(r.x), "=f"(r.y) : "l"(a)); return r;
}
__device__ __forceinline__ void fma2(u64 &d, u64 a, u64 b){
    asm("fma.rn.f32x2 %0,%1,%2,%0;" : "+l"(d) : "l"(a), "l"(b));
}

// scratch: per-(b,h) M[64][64] and s[64]
__device__ float g_M[128 * 64 * 64];
__device__ float g_S[128 * 64];

__device__ __forceinline__ float inv_softplus(const float* __restrict__ delta){
    float d = delta[0];
    float t = (d > 20.f) ? d : log1pf(expf(d));
    return 1.f / t;
}

// =====================================================================
// Kernel 1: per (b,h): M[d][e] = sum_l k'[l,d] * v[l,e],  s[d] = sum_l k'[l,d]
// grid 128, block 256 (8 warps). Warp w handles rows l = w, w+8, ...
// Lane owns d = {2*lane, 2*lane+1}; acc over all 64 e as 32 f32x2.
// =====================================================================
__global__ __launch_bounds__(256, 1) void kv_ksum_kernel(
    const float* __restrict__ Kp, const float* __restrict__ Vp,
    const float* __restrict__ delta)
{
    __shared__ float  sM[64 * 65];          // stride 65 -> 2-way conflicts max
    __shared__ float  sS[64];
    __shared__ float2 vbuf[8][2][32];       // per-warp double-buffered v row

    const int bh   = blockIdx.x;            // b*16 + h
    const int b    = bh >> 4, h = bh & 15;
    const int tid  = threadIdx.x;
    const int w    = tid >> 5, lane = tid & 31;

    for (int i = tid; i < 64 * 65; i += 256) sM[i] = 0.f;
    if (tid < 64) sS[tid] = 0.f;
    __syncthreads();

    const float invT = inv_softplus(delta);

    const long rowstride = 16L * 64L;       // H*E floats between consecutive l
    const float* kbase = Kp + ((long)b * 4096L * 16L + h) * 64L + 2 * lane;
    const float* vbase = Vp + ((long)b * 4096L * 16L + h) * 64L + 2 * lane;

    u64 acc0[32], acc1[32];
    #pragma unroll
    for (int j = 0; j < 32; j++){ acc0[j] = 0ull; acc1[j] = 0ull; }
    float s0 = 0.f, s1 = 0.f;

    int p = 0;
    long l = w;
    float2 kc = *(const float2*)(kbase + l * rowstride);
    float2 vc = *(const float2*)(vbase + l * rowstride);

    for (int it = 0; it < 512; it++){
        float2 kn, vn;
        const long ln = l + 8;
        if (it + 1 < 512){
            kn = *(const float2*)(kbase + ln * rowstride);
            vn = *(const float2*)(vbase + ln * rowstride);
        }
        // clamped temperature softmax over 64 (2 per lane)
        float a0 = (kc.x < 0.f) ? -20.f : kc.x;
        float a1 = (kc.y < 0.f) ? -20.f : kc.y;
        float m = fmaxf(a0, a1);
        #pragma unroll
        for (int o = 16; o; o >>= 1) m = fmaxf(m, __shfl_xor_sync(FULL, m, o));
        float e0 = __expf((a0 - m) * invT);
        float e1 = __expf((a1 - m) * invT);
        float sm = e0 + e1;
        #pragma unroll
        for (int o = 16; o; o >>= 1) sm += __shfl_xor_sync(FULL, sm, o);
        float rs = __fdividef(1.f, sm);
        e0 *= rs; e1 *= rs;
        s0 += e0; s1 += e1;

        vbuf[w][p][lane] = vc;
        __syncwarp();
        const u64 kk0 = pk2(e0, e0), kk1 = pk2(e1, e1);
        #pragma unroll
        for (int j = 0; j < 32; j++){
            u64 vv = *(const u64*)&vbuf[w][p][j];   // 8B broadcast
            fma2(acc0[j], kk0, vv);
            fma2(acc1[j], kk1, vv);
        }
        p ^= 1; l = ln; kc = kn; vc = vn;
    }

    // combine 8 warp-private accumulators via shared atomics
    atomicAdd(&sS[2 * lane],     s0);
    atomicAdd(&sS[2 * lane + 1], s1);
    #pragma unroll
    for (int j = 0; j < 32; j++){
        float2 a = upk2(acc0[j]);
        atomicAdd(&sM[(2 * lane)     * 65 + 2 * j    ], a.x);
        atomicAdd(&sM[(2 * lane)     * 65 + 2 * j + 1], a.y);
        float2 c = upk2(acc1[j]);
        atomicAdd(&sM[(2 * lane + 1) * 65 + 2 * j    ], c.x);
        atomicAdd(&sM[(2 * lane + 1) * 65 + 2 * j + 1], c.y);
    }
    __syncthreads();

    float* Mout = g_M + (long)bh * 4096;
    for (int i = tid; i < 4096; i += 256)
        Mout[i] = sM[(i >> 6) * 65 + (i & 63)];
    if (tid < 64) g_S[bh * 64 + tid] = sS[tid];
}

// =====================================================================
// Kernel 2: out[l,d] = z_l * sum_e q'[l,e] * M[e][d],  z_l = 1/(q'.s + eps)
// grid (128, 8), block 128 (4 warps), 128 rows per warp.
// Warp keeps M column-pair slice in registers: Mreg[e] = {M[e][2l],M[e][2l+1]}.
// =====================================================================
__global__ __launch_bounds__(128) void out_kernel(
    const float* __restrict__ Qp, float* __restrict__ Out,
    const float* __restrict__ delta)
{
    const int bh   = blockIdx.x;
    const int b    = bh >> 4, h = bh & 15;
    const int c    = blockIdx.y;            // L-chunk 0..7
    const int tid  = threadIdx.x;
    const int w    = tid >> 5, lane = tid & 31;

    const float invT = inv_softplus(delta);

    // load M slice into registers (coalesced 256B per e)
    const float* Mrow = g_M + (long)bh * 4096 + 2 * lane;
    u64 Mreg[64];
    #pragma unroll
    for (int e = 0; e < 64; e++)
        Mreg[e] = *(const u64*)(Mrow + e * 64);
    const float2 s2 = *(const float2*)(g_S + bh * 64 + 2 * lane);

    const long rowstride = 16L * 64L;
    const long base = ((long)b * 4096L * 16L + h) * 64L + 2 * lane;
    long l = (long)c * 512 + (long)w * 128;

    float2 qc = *(const float2*)(Qp + base + l * rowstride);

    for (int it = 0; it < 128; it++){
        float2 qn;
        if (it + 1 < 128)
            qn = *(const float2*)(Qp + base + (l + 1) * rowstride);

        float a0 = (qc.x < 0.f) ? -20.f : qc.x;
        float a1 = (qc.y < 0.f) ? -20.f : qc.y;
        float m = fmaxf(a0, a1);
        #pragma unroll
        for (int o = 16; o; o >>= 1) m = fmaxf(m, __shfl_xor_sync(FULL, m, o));
        float e0 = __expf((a0 - m) * invT);
        float e1 = __expf((a1 - m) * invT);
        float sm = e0 + e1;
        #pragma unroll
        for (int o = 16; o; o >>= 1) sm += __shfl_xor_sync(FULL, sm, o);
        float rs = __fdividef(1.f, sm);
        e0 *= rs; e1 *= rs;                 // q' (2 per lane)

        // z = 1/(q'.s + eps), folded into q'
        float dot = e0 * s2.x + e1 * s2.y;
        #pragma unroll
        for (int o = 16; o; o >>= 1) dot += __shfl_xor_sync(FULL, dot, o);
        float z = __fdividef(1.f, dot + 1e-6f);
        e0 *= z; e1 *= z;

        // out[d] = sum_e q''[e] * M[e][d]   (d = 2*lane, 2*lane+1)
        u64 o2 = 0ull;
        #pragma unroll
        for (int j = 0; j < 32; j++){
            float qa = __shfl_sync(FULL, e0, j);   // q''[2j]
            float qb = __shfl_sync(FULL, e1, j);   // q''[2j+1]
            fma2(o2, pk2(qa, qa), Mreg[2 * j]);
            fma2(o2, pk2(qb, qb), Mreg[2 * j + 1]);
        }
        float2 ov = upk2(o2);
        *(float2*)(Out + base + l * rowstride) = ov;

        l += 1; qc = qn;
    }
}

extern "C" void kernel_launch(void* const* d_in, const int* in_sizes, int n_in,
                              void* d_out, int out_size)
{
    const float* Q     = (const float*)d_in[0];
    const float* K     = (const float*)d_in[1];
    const float* V     = (const float*)d_in[2];
    const float* delta = (const float*)d_in[3];
    float* Out = (float*)d_out;

    kv_ksum_kernel<<<128, 256>>>(K, V, delta);
    out_kernel<<<dim3(128, 8), 128>>>(Q, Out, delta);
}

// round 2
// speedup vs baseline: 1.1663x; 1.1663x over previous
#include <cuda_runtime.h>

typedef unsigned long long u64;
#define FULL 0xFFFFFFFFu

// ---- packed f32x2 helpers (Blackwell) ----
__device__ __forceinline__ u64 pk2(float x, float y){
    u64 r; asm("mov.b64 %0,{%1,%2};" : "=l"(r) : "f"(x), "f"(y)); return r;
}
__device__ __forceinline__ float2 upk2(u64 a){
    float2 r; asm("mov.b64 {%0,%1},%2;" : "=f"(r.x), "=f"(r.y) : "l"(a)); return r;
}
__device__ __forceinline__ void fma2(u64 &d, u64 a, u64 b){
    asm("fma.rn.f32x2 %0,%1,%2,%0;" : "+l"(d) : "l"(a), "l"(b));
}

// scratch: per-(b,h) KV[64][64] (k-dim major) and s[64]
__device__ float g_M[128 * 64 * 64];
__device__ float g_S[128 * 64];

__device__ __forceinline__ float inv_softplus(const float* __restrict__ delta){
    float d = delta[0];
    float t = (d > 20.f) ? d : log1pf(expf(d));
    return 1.f / t;
}

__global__ void zero_kernel(){
    const int n = 128*64*64 + 128*64;
    for (int i = blockIdx.x * blockDim.x + threadIdx.x; i < n; i += gridDim.x * blockDim.x){
        if (i < 128*64*64) g_M[i] = 0.f;
        else               g_S[i - 128*64*64] = 0.f;
    }
}

// =====================================================================
// Kernel 1: per (b,h): KV[d][e] = sum_l k'[l,d]*v[l,e],  s[d] = sum_l k'[l,d]
// grid 512 (4 CTAs per bh), block 128 (4 warps = 2 pairs).
// Pair p handles rows [q4*1024 + p*512, +512). Within a pair, warp half=0
// accumulates e in [0,32), half=1 e in [32,64). Lane owns d0=2*lane, d1=2*lane+1.
// Both warps of a pair compute the same softmax (cheap) to halve reg pressure.
// =====================================================================
__global__ __launch_bounds__(128, 4) void kv_kernel(
    const float* __restrict__ Kp, const float* __restrict__ Vp,
    const float* __restrict__ delta)
{
    __shared__ float sM[64 * 65];          // [d][e], stride 65
    __shared__ float sS[64];
    __shared__ float vbuf[4][2][32];       // per-warp double-buffered v half-row

    const int bx   = blockIdx.x;
    const int bh   = bx >> 2;
    const int q4   = bx & 3;
    const int b    = bh >> 4, h = bh & 15;
    const int tid  = threadIdx.x;
    const int w    = tid >> 5, lane = tid & 31;
    const int pair = w >> 1, half = w & 1;
    const int eoff = half * 32;

    const float invT = inv_softplus(delta);

    const float* kbase = Kp + ((long)b * 4096L * 16L + h) * 64L;
    const float* vbase = Vp + ((long)b * 4096L * 16L + h) * 64L;

    u64 accA[16], accB[16];
    #pragma unroll
    for (int j = 0; j < 16; j++){ accA[j] = 0ull; accB[j] = 0ull; }
    float s0 = 0.f, s1 = 0.f;

    long l = (long)q4 * 1024 + (long)pair * 512;
    int p = 0;
    float2 kc = *(const float2*)(kbase + l * 1024 + 2 * lane);
    float  vc = vbase[l * 1024 + eoff + lane];

    for (int it = 0; it < 512; it++){
        float2 kn; float vn;
        if (it + 1 < 512){
            kn = *(const float2*)(kbase + (l + 1) * 1024 + 2 * lane);
            vn = vbase[(l + 1) * 1024 + eoff + lane];
        }
        // clamped temperature softmax over 64 k-dims (2 per lane)
        float a0 = (kc.x < 0.f) ? -20.f : kc.x;
        float a1 = (kc.y < 0.f) ? -20.f : kc.y;
        float m = fmaxf(a0, a1);
        #pragma unroll
        for (int o = 16; o; o >>= 1) m = fmaxf(m, __shfl_xor_sync(FULL, m, o));
        float e0 = __expf((a0 - m) * invT);
        float e1 = __expf((a1 - m) * invT);
        float sm = e0 + e1;
        #pragma unroll
        for (int o = 16; o; o >>= 1) sm += __shfl_xor_sync(FULL, sm, o);
        float rs = __fdividef(1.f, sm);
        e0 *= rs; e1 *= rs;
        s0 += e0; s1 += e1;

        vbuf[w][p][lane] = vc;
        __syncwarp();
        const u64 kk0 = pk2(e0, e0), kk1 = pk2(e1, e1);
        #pragma unroll
        for (int j = 0; j < 16; j++){
            u64 vv = *(const u64*)&vbuf[w][p][2 * j];   // (v[eoff+2j], v[eoff+2j+1])
            fma2(accA[j], kk0, vv);
            fma2(accB[j], kk1, vv);
        }
        p ^= 1; l++; kc = kn; vc = vn;
    }

    // ---- combine: pair0 plain store, pair1 atomic add, then RED to gmem ----
    const int d0 = 2 * lane, d1 = 2 * lane + 1;
    __syncthreads();
    if (w < 2){
        #pragma unroll
        for (int j = 0; j < 16; j++){
            float2 a = upk2(accA[j]);
            sM[d0 * 65 + eoff + 2 * j    ] = a.x;
            sM[d0 * 65 + eoff + 2 * j + 1] = a.y;
            float2 c = upk2(accB[j]);
            sM[d1 * 65 + eoff + 2 * j    ] = c.x;
            sM[d1 * 65 + eoff + 2 * j + 1] = c.y;
        }
        if (half == 0){ sS[d0] = s0; sS[d1] = s1; }
    }
    __syncthreads();
    if (w >= 2){
        #pragma unroll
        for (int j = 0; j < 16; j++){
            float2 a = upk2(accA[j]);
            atomicAdd(&sM[d0 * 65 + eoff + 2 * j    ], a.x);
            atomicAdd(&sM[d0 * 65 + eoff + 2 * j + 1], a.y);
            float2 c = upk2(accB[j]);
            atomicAdd(&sM[d1 * 65 + eoff + 2 * j    ], c.x);
            atomicAdd(&sM[d1 * 65 + eoff + 2 * j + 1], c.y);
        }
        if (half == 0){ atomicAdd(&sS[d0], s0); atomicAdd(&sS[d1], s1); }
    }
    __syncthreads();

    float* Mout = g_M + (long)bh * 4096;
    for (int i = tid; i < 4096; i += 128)
        atomicAdd(&Mout[i], sM[(i >> 6) * 65 + (i & 63)]);
    if (tid < 64) atomicAdd(&g_S[bh * 64 + tid], sS[tid]);
}

// =====================================================================
// Kernel 2: out[l,e] = sum_d q''[l,d] * KV[d][e],  q'' = e/(u + eps*sm)
// grid (128 bh, 16 chunks), block 128 (4 warps), 64 rows per warp.
// Lane owns output pair (2*lane, 2*lane+1). M slice pre-paired in registers:
// MA[j] = (KV[2j][e0], KV[2j+1][e0]) so one fma2 covers 2 contraction terms.
// q'' pairs broadcast via 8B LDS (no shuffles, no dup-MOVs in inner loop).
// =====================================================================
__global__ __launch_bounds__(128, 3) void out_kernel(
    const float* __restrict__ Qp, float* __restrict__ Out,
    const float* __restrict__ delta)
{
    __shared__ float2 qbuf[4][2][32];

    const int bh   = blockIdx.x;
    const int b    = bh >> 4, h = bh & 15;
    const int ck   = blockIdx.y;
    const int tid  = threadIdx.x;
    const int w    = tid >> 5, lane = tid & 31;

    const float invT = inv_softplus(delta);

    // register M slice, paired along the contraction (k) dim
    const float* gM = g_M + (long)bh * 4096;
    const int e0i = 2 * lane, e1i = 2 * lane + 1;
    u64 MA[32], MB[32];
    #pragma unroll
    for (int j = 0; j < 32; j++){
        MA[j] = pk2(gM[(2 * j) * 64 + e0i], gM[(2 * j + 1) * 64 + e0i]);
        MB[j] = pk2(gM[(2 * j) * 64 + e1i], gM[(2 * j + 1) * 64 + e1i]);
    }
    const float2 s2 = *(const float2*)(g_S + bh * 64 + 2 * lane);

    const long base = ((long)b * 4096L * 16L + h) * 64L + 2 * lane;
    long l = (long)ck * 256 + (long)w * 64;
    int p = 0;

    float2 qc = *(const float2*)(Qp + base + l * 1024);

    for (int it = 0; it < 64; it++){
        float2 qn;
        if (it + 1 < 64)
            qn = *(const float2*)(Qp + base + (l + 1) * 1024);

        float a0 = (qc.x < 0.f) ? -20.f : qc.x;
        float a1 = (qc.y < 0.f) ? -20.f : qc.y;
        float m = fmaxf(a0, a1);
        #pragma unroll
        for (int o = 16; o; o >>= 1) m = fmaxf(m, __shfl_xor_sync(FULL, m, o));
        float e0 = __expf((a0 - m) * invT);
        float e1 = __expf((a1 - m) * invT);
        float sm = e0 + e1;
        float u  = e0 * s2.x + e1 * s2.y;   // unnormalized q.k_sum
        #pragma unroll
        for (int o = 16; o; o >>= 1){       // two interleaved chains
            sm += __shfl_xor_sync(FULL, sm, o);
            u  += __shfl_xor_sync(FULL, u,  o);
        }
        // q'' = e / (u + eps*sm)  ==  softmax(q)/T-normalized * z  (single divide)
        float f = __fdividef(1.f, u + 1e-6f * sm);
        e0 *= f; e1 *= f;

        qbuf[w][p][lane] = make_float2(e0, e1);
        __syncwarp();

        u64 oA = 0ull, oB = 0ull;
        #pragma unroll
        for (int j = 0; j < 32; j++){
            u64 qp = *(const u64*)&qbuf[w][p][j];   // (q''[2j], q''[2j+1]) broadcast
            fma2(oA, qp, MA[j]);
            fma2(oB, qp, MB[j]);
        }
        float2 A = upk2(oA), B = upk2(oB);
        *(float2*)(Out + base + l * 1024) = make_float2(A.x + A.y, B.x + B.y);

        p ^= 1; l++; qc = qn;
    }
}

extern "C" void kernel_launch(void* const* d_in, const int* in_sizes, int n_in,
                              void* d_out, int out_size)
{
    const float* Q     = (const float*)d_in[0];
    const float* K     = (const float*)d_in[1];
    const float* V     = (const float*)d_in[2];
    const float* delta = (const float*)d_in[3];
    float* Out = (float*)d_out;

    zero_kernel<<<256, 256>>>();
    kv_kernel<<<512, 128>>>(K, V, delta);
    out_kernel<<<dim3(128, 16), 128>>>(Q, Out, delta);
}

// round 3
// speedup vs baseline: 1.9486x; 1.6708x over previous
#include <cuda_runtime.h>

typedef unsigned long long u64;
#define FULL 0xFFFFFFFFu

// ---- packed f32x2 + fast-math helpers (Blackwell) ----
__device__ __forceinline__ u64 pk2(float x, float y){
    u64 r; asm("mov.b64 %0,{%1,%2};" : "=l"(r) : "f"(x), "f"(y)); return r;
}
__device__ __forceinline__ float2 upk2(u64 a){
    float2 r; asm("mov.b64 {%0,%1},%2;" : "=f"(r.x), "=f"(r.y) : "l"(a)); return r;
}
__device__ __forceinline__ void fma2(u64 &d, u64 a, u64 b){
    asm("fma.rn.f32x2 %0,%1,%2,%0;" : "+l"(d) : "l"(a), "l"(b));
}
__device__ __forceinline__ float ex2(float x){
    float r; asm("ex2.approx.f32 %0,%1;" : "=f"(r) : "f"(x)); return r;
}
__device__ __forceinline__ float frcp(float x){
    float r; asm("rcp.approx.f32 %0,%1;" : "=f"(r) : "f"(x)); return r;
}

// scratch: per-(b,h) KV[64][64] (k-dim major) and s[64]
__device__ float g_M[128 * 64 * 64];
__device__ float g_S[128 * 64];

// cT = log2(e) / softplus(delta)
__device__ __forceinline__ float get_cT(const float* __restrict__ delta){
    float d = delta[0];
    float t = (d > 20.f) ? d : log1pf(expf(d));
    return 1.44269504088896f / t;
}

__global__ void zero_kernel(){
    const int n = 128*64*64 + 128*64;
    for (int i = blockIdx.x * blockDim.x + threadIdx.x; i < n; i += gridDim.x * blockDim.x){
        if (i < 128*64*64) g_M[i] = 0.f;
        else               g_S[i - 128*64*64] = 0.f;
    }
}

// =====================================================================
// Kernel 1: KV[d][e] = sum_l k'[l,d]*v[l,e],  s[d] = sum_l k'[l,d]
// grid 512 (4 CTAs/bh), block 128 (4 warps = 2 pairs). Pair p owns 512 rows,
// processed 2-at-a-time (l, l+256) for ILP. Warp half owns e in [32h,32h+32).
// Lane owns d pair (2*lane, 2*lane+1). No max-subtraction (range-safe).
// =====================================================================
__global__ __launch_bounds__(128, 4) void kv_kernel(
    const float* __restrict__ Kp, const float* __restrict__ Vp,
    const float* __restrict__ delta)
{
    __shared__ float sM[64 * 65];
    __shared__ float sS[64];
    __shared__ float vbuf[4][2][32];       // [warp][row-slot][lane]

    const int bx   = blockIdx.x;
    const int bh   = bx >> 2;
    const int q4   = bx & 3;
    const int b    = bh >> 4, h = bh & 15;
    const int tid  = threadIdx.x;
    const int w    = tid >> 5, lane = tid & 31;
    const int pair = w >> 1, half = w & 1;
    const int eoff = half * 32;

    const float cT = get_cT(delta);

    const float* kbase = Kp + ((long)b * 4096L * 16L + h) * 64L + 2 * lane;
    const float* vbase = Vp + ((long)b * 4096L * 16L + h) * 64L + eoff + lane;

    u64 accA[16], accB[16];
    #pragma unroll
    for (int j = 0; j < 16; j++){ accA[j] = 0ull; accB[j] = 0ull; }
    float s0 = 0.f, s1 = 0.f;

    const long base = (long)q4 * 1024 + (long)pair * 512;
    float2 kc1 = *(const float2*)(kbase + base * 1024);
    float2 kc2 = *(const float2*)(kbase + (base + 256) * 1024);
    float  vc1 = vbase[base * 1024];
    float  vc2 = vbase[(base + 256) * 1024];

    for (int it = 0; it < 256; it++){
        float2 kn1, kn2; float vn1, vn2;
        if (it + 1 < 256){
            const long l1 = base + it + 1, l2 = l1 + 256;
            kn1 = *(const float2*)(kbase + l1 * 1024);
            kn2 = *(const float2*)(kbase + l2 * 1024);
            vn1 = vbase[l1 * 1024];
            vn2 = vbase[l2 * 1024];
        }
        vbuf[w][0][lane] = vc1;
        vbuf[w][1][lane] = vc2;
        __syncwarp();

        // two independent softmax chains (no max-subtract)
        float a0 = (kc1.x < 0.f) ? -20.f : kc1.x;
        float a1 = (kc1.y < 0.f) ? -20.f : kc1.y;
        float b0 = (kc2.x < 0.f) ? -20.f : kc2.x;
        float b1 = (kc2.y < 0.f) ? -20.f : kc2.y;
        float e0 = ex2(a0 * cT), e1 = ex2(a1 * cT);
        float f0 = ex2(b0 * cT), f1 = ex2(b1 * cT);
        float sm1 = e0 + e1, sm2 = f0 + f1;
        #pragma unroll
        for (int o = 16; o; o >>= 1){
            sm1 += __shfl_xor_sync(FULL, sm1, o);
            sm2 += __shfl_xor_sync(FULL, sm2, o);
        }
        float rs1 = frcp(sm1), rs2 = frcp(sm2);
        e0 *= rs1; e1 *= rs1; f0 *= rs2; f1 *= rs2;
        s0 += e0 + f0; s1 += e1 + f1;

        const u64 kA1 = pk2(e0, e0), kB1 = pk2(e1, e1);
        const u64 kA2 = pk2(f0, f0), kB2 = pk2(f1, f1);
        #pragma unroll
        for (int j = 0; j < 16; j++){
            u64 v1 = *(const u64*)&vbuf[w][0][2 * j];
            u64 v2 = *(const u64*)&vbuf[w][1][2 * j];
            fma2(accA[j], kA1, v1); fma2(accA[j], kA2, v2);
            fma2(accB[j], kB1, v1); fma2(accB[j], kB2, v2);
        }
        __syncwarp();
        kc1 = kn1; kc2 = kn2; vc1 = vn1; vc2 = vn2;
    }

    // ---- combine: warps 0,1 store, warps 2,3 atomic-add, then add to gmem ----
    const int d0 = 2 * lane, d1 = 2 * lane + 1;
    __syncthreads();
    if (w < 2){
        #pragma unroll
        for (int j = 0; j < 16; j++){
            float2 a = upk2(accA[j]);
            sM[d0 * 65 + eoff + 2 * j    ] = a.x;
            sM[d0 * 65 + eoff + 2 * j + 1] = a.y;
            float2 c = upk2(accB[j]);
            sM[d1 * 65 + eoff + 2 * j    ] = c.x;
            sM[d1 * 65 + eoff + 2 * j + 1] = c.y;
        }
        if (half == 0){ sS[d0] = s0; sS[d1] = s1; }
    }
    __syncthreads();
    if (w >= 2){
        #pragma unroll
        for (int j = 0; j < 16; j++){
            float2 a = upk2(accA[j]);
            atomicAdd(&sM[d0 * 65 + eoff + 2 * j    ], a.x);
            atomicAdd(&sM[d0 * 65 + eoff + 2 * j + 1], a.y);
            float2 c = upk2(accB[j]);
            atomicAdd(&sM[d1 * 65 + eoff + 2 * j    ], c.x);
            atomicAdd(&sM[d1 * 65 + eoff + 2 * j + 1], c.y);
        }
        if (half == 0){ atomicAdd(&sS[d0], s0); atomicAdd(&sS[d1], s1); }
    }
    __syncthreads();

    float* Mout = g_M + (long)bh * 4096;
    for (int i = tid; i < 4096; i += 128)
        atomicAdd(&Mout[i], sM[(i >> 6) * 65 + (i & 63)]);
    if (tid < 64) atomicAdd(&g_S[bh * 64 + tid], sS[tid]);
}

// =====================================================================
// Kernel 2: out[l,e] = sum_d q''[l,d]*KV[d][e],  q'' = exp/(u + eps*sm)
// grid (128 bh, 8 chunks), block 128 (4 warps). Warp owns 128 rows,
// processed 2-at-a-time (l, l+64). Lane owns outputs (2*lane, 2*lane+1),
// M slice register-resident, paired along d so one fma2 = 2 MACs.
// =====================================================================
__global__ __launch_bounds__(128, 3) void out_kernel(
    const float* __restrict__ Qp, float* __restrict__ Out,
    const float* __restrict__ delta)
{
    __shared__ float2 qbuf[4][2][32];

    const int bh   = blockIdx.x;
    const int b    = bh >> 4, h = bh & 15;
    const int ck   = blockIdx.y;
    const int tid  = threadIdx.x;
    const int w    = tid >> 5, lane = tid & 31;

    const float cT = get_cT(delta);

    const float* gM = g_M + (long)bh * 4096;
    const int e0i = 2 * lane, e1i = 2 * lane + 1;
    u64 MA[32], MB[32];
    #pragma unroll
    for (int j = 0; j < 32; j++){
        MA[j] = pk2(gM[(2 * j) * 64 + e0i], gM[(2 * j + 1) * 64 + e0i]);
        MB[j] = pk2(gM[(2 * j) * 64 + e1i], gM[(2 * j + 1) * 64 + e1i]);
    }
    const float2 s2 = *(const float2*)(g_S + bh * 64 + 2 * lane);

    const long basep = ((long)b * 4096L * 16L + h) * 64L + 2 * lane;
    const long l0 = (long)ck * 512 + (long)w * 128;

    float2 qc1 = *(const float2*)(Qp + basep + l0 * 1024);
    float2 qc2 = *(const float2*)(Qp + basep + (l0 + 64) * 1024);

    for (int it = 0; it < 64; it++){
        float2 qn1, qn2;
        if (it + 1 < 64){
            qn1 = *(const float2*)(Qp + basep + (l0 + it + 1) * 1024);
            qn2 = *(const float2*)(Qp + basep + (l0 + it + 65) * 1024);
        }

        float a0 = (qc1.x < 0.f) ? -20.f : qc1.x;
        float a1 = (qc1.y < 0.f) ? -20.f : qc1.y;
        float b0 = (qc2.x < 0.f) ? -20.f : qc2.x;
        float b1 = (qc2.y < 0.f) ? -20.f : qc2.y;
        float e0 = ex2(a0 * cT), e1 = ex2(a1 * cT);
        float f0 = ex2(b0 * cT), f1 = ex2(b1 * cT);

        float sm1 = e0 + e1,                 sm2 = f0 + f1;
        float u1  = e0 * s2.x + e1 * s2.y,   u2  = f0 * s2.x + f1 * s2.y;
        #pragma unroll
        for (int o = 16; o; o >>= 1){        // 4 interleaved chains
            sm1 += __shfl_xor_sync(FULL, sm1, o);
            u1  += __shfl_xor_sync(FULL, u1,  o);
            sm2 += __shfl_xor_sync(FULL, sm2, o);
            u2  += __shfl_xor_sync(FULL, u2,  o);
        }
        float g1 = frcp(u1 + 1e-6f * sm1);   // = z / sm (single divide)
        float g2 = frcp(u2 + 1e-6f * sm2);
        e0 *= g1; e1 *= g1; f0 *= g2; f1 *= g2;

        qbuf[w][0][lane] = make_float2(e0, e1);
        qbuf[w][1][lane] = make_float2(f0, f1);
        __syncwarp();

        u64 oA = 0ull, oB = 0ull, pA = 0ull, pB = 0ull;
        #pragma unroll
        for (int j = 0; j < 32; j++){
            u64 q1 = *(const u64*)&qbuf[w][0][j];   // broadcast
            u64 q2 = *(const u64*)&qbuf[w][1][j];
            fma2(oA, q1, MA[j]); fma2(oB, q1, MB[j]);
            fma2(pA, q2, MA[j]); fma2(pB, q2, MB[j]);
        }
        __syncwarp();
        float2 A = upk2(oA), B = upk2(oB);
        float2 C = upk2(pA), D = upk2(pB);
        *(float2*)(Out + basep + (l0 + it) * 1024)      = make_float2(A.x + A.y, B.x + B.y);
        *(float2*)(Out + basep + (l0 + it + 64) * 1024) = make_float2(C.x + C.y, D.x + D.y);

        qc1 = qn1; qc2 = qn2;
    }
}

extern "C" void kernel_launch(void* const* d_in, const int* in_sizes, int n_in,
                              void* d_out, int out_size)
{
    const float* Q     = (const float*)d_in[0];
    const float* K     = (const float*)d_in[1];
    const float* V     = (const float*)d_in[2];
    const float* delta = (const float*)d_in[3];
    float* Out = (float*)d_out;

    zero_kernel<<<256, 256>>>();
    kv_kernel<<<512, 128>>>(K, V, delta);
    out_kernel<<<dim3(128, 8), 128>>>(Q, Out, delta);
}

// round 4
// speedup vs baseline: 2.3438x; 1.2028x over previous
#include <cuda_runtime.h>

typedef unsigned long long u64;
#define FULL 0xFFFFFFFFu

__device__ __forceinline__ u64 pk2(float x, float y){
    u64 r; asm("mov.b64 %0,{%1,%2};" : "=l"(r) : "f"(x), "f"(y)); return r;
}
__device__ __forceinline__ float2 upk2(u64 a){
    float2 r; asm("mov.b64 {%0,%1},%2;" : "=f"(r.x), "=f"(r.y) : "l"(a)); return r;
}
__device__ __forceinline__ void fma2(u64 &d, u64 a, u64 b){
    asm("fma.rn.f32x2 %0,%1,%2,%0;" : "+l"(d) : "l"(a), "l"(b));
}
__device__ __forceinline__ float ex2(float x){
    float r; asm("ex2.approx.f32 %0,%1;" : "=f"(r) : "f"(x)); return r;
}
__device__ __forceinline__ float frcp(float x){
    float r; asm("rcp.approx.f32 %0,%1;" : "=f"(r) : "f"(x)); return r;
}

// per-CTA partials: [bh*4 + q4] slices
__device__ float g_Mp[512 * 4096];
__device__ float g_Sp[512 * 64];

// cT = log2(e) / softplus(delta)
__device__ __forceinline__ float get_cT(const float* __restrict__ delta){
    float d = delta[0];
    float t = (d > 20.f) ? d : log1pf(expf(d));
    return 1.44269504088896f / t;
}

#define BAR_PAIR(id) asm volatile("bar.sync %0, 64;" :: "r"(id) : "memory")

// =====================================================================
// Kernel 1: partial KV[d][e] and s[d] per (bh, quarter-of-L).
// grid 512, block 128 = 2 pairs of warps. Pair owns 512 rows as 16 tiles
// of 32. Phase A: coalesced tile load (k by half0 warp, v by half1).
// Phase B: softmax with lane-pair-per-row (one shfl). Phase C: rank-1
// accumulation, lane owns d-pair, warp-half owns e-half.
// =====================================================================
__global__ __launch_bounds__(128, 4) void kv_kernel(
    const float* __restrict__ Kp, const float* __restrict__ Vp,
    const float* __restrict__ delta)
{
    __shared__ float pool[8832];   // [0,4352): k tiles, [4352,8704): v tiles, [8704,8768): rs

    const int bx   = blockIdx.x;
    const int bh   = bx >> 2;
    const int q4   = bx & 3;
    const int b    = bh >> 4, h = bh & 15;
    const int tid  = threadIdx.x;
    const int w    = tid >> 5, lane = tid & 31;
    const int pair = w >> 1, half = w & 1;
    const int eoff = half * 32;

    float* skt = pool + pair * 2176;
    float* svt = pool + 4352 + pair * 2176;
    float* sgp = pool + 8704 + pair * 32;

    const float cT = get_cT(delta);

    const long cbase = ((long)b * 4096L) * 1024L + h * 64L;
    const float* kb = Kp + cbase;
    const float* vb = Vp + cbase;

    u64 accA[16], accB[16];
    #pragma unroll
    for (int j = 0; j < 16; j++){ accA[j] = 0ull; accB[j] = 0ull; }
    float s0 = 0.f, s1 = 0.f;

    const int r_ld = lane >> 4;          // 0/1: two rows per LDG pass
    const int c_ld = (lane & 15) * 4;

    for (int t = 0; t < 16; t++){
        const long l0 = (long)q4 * 1024 + (long)pair * 512 + t * 32;

        // ---- Phase A: half0 loads k tile, half1 loads v tile (coalesced) ----
        {
            const float* src = half ? vb : kb;
            float* dst = half ? svt : skt;
            #pragma unroll
            for (int i = 0; i < 16; i++){
                const int r = 2 * i + r_ld;
                float4 v4 = *(const float4*)(src + (l0 + r) * 1024 + c_ld);
                *(float4*)(dst + r * 68 + c_ld) = v4;
            }
        }
        BAR_PAIR(1 + pair);

        // ---- Phase B: exp (unnormalized) in place; rs per row. 2 lanes/row ----
        {
            const int r  = half * 16 + (lane >> 1);
            float* rowp = skt + r * 68 + (lane & 1) * 32;
            float smA = 0.f, smB = 0.f;
            #pragma unroll
            for (int c = 0; c < 8; c++){
                float4 f = *(float4*)(rowp + 4 * c);
                f.x = ex2(cT * ((f.x < 0.f) ? -20.f : f.x));
                f.y = ex2(cT * ((f.y < 0.f) ? -20.f : f.y));
                f.z = ex2(cT * ((f.z < 0.f) ? -20.f : f.z));
                f.w = ex2(cT * ((f.w < 0.f) ? -20.f : f.w));
                *(float4*)(rowp + 4 * c) = f;
                smA += f.x + f.y; smB += f.z + f.w;
            }
            float sm = smA + smB;
            sm += __shfl_xor_sync(FULL, sm, 1);
            if ((lane & 1) == 0) sgp[r] = frcp(sm);
        }
        BAR_PAIR(1 + pair);

        // ---- Phase C: acc[d][e] += k''[d] * v[e] over 32 rows ----
        #pragma unroll 4
        for (int r = 0; r < 32; r++){
            float2 kp = *(const float2*)(skt + r * 68 + 2 * lane);
            float rs = sgp[r];
            float k0 = kp.x * rs, k1 = kp.y * rs;
            const u64 kk0 = pk2(k0, k0), kk1 = pk2(k1, k1);
            s0 += k0; s1 += k1;
            const float* vrow = svt + r * 68 + eoff;
            #pragma unroll
            for (int j = 0; j < 16; j++){
                u64 vv = *(const u64*)(vrow + 2 * j);
                fma2(accA[j], kk0, vv);
                fma2(accB[j], kk1, vv);
            }
        }
        BAR_PAIR(1 + pair);
    }

    // ---- combine pairs in smem (alias pool), write per-CTA partial ----
    __syncthreads();
    float* sM  = pool;            // 64 x 66
    float* sSh = pool + 4224;     // 64
    const int d0 = 2 * lane, d1 = d0 + 1;
    if (pair == 0){
        #pragma unroll
        for (int j = 0; j < 16; j++){
            *(float2*)&sM[d0 * 66 + eoff + 2 * j] = upk2(accA[j]);
            *(float2*)&sM[d1 * 66 + eoff + 2 * j] = upk2(accB[j]);
        }
        if (half == 0){ sSh[d0] = s0; sSh[d1] = s1; }
    }
    __syncthreads();
    if (pair == 1){
        #pragma unroll
        for (int j = 0; j < 16; j++){
            float2 a = upk2(accA[j]);
            float2 c0 = *(float2*)&sM[d0 * 66 + eoff + 2 * j];
            c0.x += a.x; c0.y += a.y;
            *(float2*)&sM[d0 * 66 + eoff + 2 * j] = c0;
            float2 c = upk2(accB[j]);
            float2 c1 = *(float2*)&sM[d1 * 66 + eoff + 2 * j];
            c1.x += c.x; c1.y += c.y;
            *(float2*)&sM[d1 * 66 + eoff + 2 * j] = c1;
        }
        if (half == 0){ sSh[d0] += s0; sSh[d1] += s1; }
    }
    __syncthreads();
    float* Mout = g_Mp + (long)bx * 4096;
    for (int i = tid; i < 4096; i += 128)
        Mout[i] = sM[(i >> 6) * 66 + (i & 63)];
    if (tid < 64) g_Sp[bx * 64 + tid] = sSh[tid];
}

// =====================================================================
// Kernel 2: out[l] = g_l * (E_l @ M), g = 1/(u + eps*sm), u = E.s, sm = sum E.
// grid (128 bh, 3), block 128 (4 independent warps). Warp streams 32-row
// tiles strided by 12 across the bh. Lane-per-row softmax (no shuffles),
// M register-resident paired along d (summing the 4 kv partials on load).
// =====================================================================
__global__ __launch_bounds__(128, 3) void out_kernel(
    const float* __restrict__ Qp, float* __restrict__ Out,
    const float* __restrict__ delta)
{
    __shared__ float sq[4][2176];
    __shared__ float sg[4][32];
    __shared__ float sSh[64];

    const int bh   = blockIdx.x;
    const int b    = bh >> 4, h = bh & 15;
    const int ck   = blockIdx.y;
    const int tid  = threadIdx.x;
    const int w    = tid >> 5, lane = tid & 31;

    const float cT = get_cT(delta);

    if (tid < 64){
        float s = 0.f;
        #pragma unroll
        for (int p = 0; p < 4; p++) s += g_Sp[(bh * 4 + p) * 64 + tid];
        sSh[tid] = s;
    }
    __syncthreads();

    // register M, partial-summed, paired along d
    u64 MA[32], MB[32];
    {
        const float* mp = g_Mp + (long)bh * 4 * 4096 + 2 * lane;
        #pragma unroll
        for (int j = 0; j < 32; j++){
            float2 r0 = make_float2(0.f, 0.f), r1 = make_float2(0.f, 0.f);
            #pragma unroll
            for (int p = 0; p < 4; p++){
                float2 a = *(const float2*)(mp + p * 4096 + (2 * j) * 64);
                float2 c = *(const float2*)(mp + p * 4096 + (2 * j + 1) * 64);
                r0.x += a.x; r0.y += a.y; r1.x += c.x; r1.y += c.y;
            }
            MA[j] = pk2(r0.x, r1.x);   // (M[2j][e0], M[2j+1][e0])
            MB[j] = pk2(r0.y, r1.y);   // (M[2j][e1], M[2j+1][e1])
        }
    }

    float* sqw = sq[w];
    const long cbase = ((long)b * 4096L) * 1024L + h * 64L;
    const int r_ld = lane >> 4;
    const int c_ld = (lane & 15) * 4;

    for (int t = ck * 4 + w; t < 128; t += 12){
        const long l0 = (long)t * 32;

        // ---- Phase A: coalesced tile load ----
        #pragma unroll
        for (int i = 0; i < 16; i++){
            const int r = 2 * i + r_ld;
            float4 v4 = *(const float4*)(Qp + cbase + (l0 + r) * 1024 + c_ld);
            *(float4*)(sqw + r * 68 + c_ld) = v4;
        }
        __syncwarp();

        // ---- Phase B: lane-per-row exp + sums, no shuffles ----
        {
            float* rowp = sqw + lane * 68;
            float sm0 = 0.f, sm1 = 0.f, u0 = 0.f, u1 = 0.f;
            #pragma unroll
            for (int c = 0; c < 16; c++){
                float4 f = *(float4*)(rowp + 4 * c);
                float4 s4 = *(const float4*)(sSh + 4 * c);   // broadcast
                f.x = ex2(cT * ((f.x < 0.f) ? -20.f : f.x));
                f.y = ex2(cT * ((f.y < 0.f) ? -20.f : f.y));
                f.z = ex2(cT * ((f.z < 0.f) ? -20.f : f.z));
                f.w = ex2(cT * ((f.w < 0.f) ? -20.f : f.w));
                *(float4*)(rowp + 4 * c) = f;
                sm0 += f.x + f.y;        sm1 += f.z + f.w;
                u0 = fmaf(f.x, s4.x, fmaf(f.y, s4.y, u0));
                u1 = fmaf(f.z, s4.z, fmaf(f.w, s4.w, u1));
            }
            sg[w][lane] = frcp((u0 + u1) + 1e-6f * (sm0 + sm1));
        }
        __syncwarp();

        // ---- Phase C: matvec per row, lane owns e-pair ----
        #pragma unroll 2
        for (int r = 0; r < 32; r++){
            const float* qr = sqw + r * 68;
            u64 oA = 0ull, oB = 0ull;
            #pragma unroll
            for (int j = 0; j < 32; j++){
                u64 qp = *(const u64*)(qr + 2 * j);   // broadcast pair
                fma2(oA, qp, MA[j]);
                fma2(oB, qp, MB[j]);
            }
            float g = sg[w][r];
            float2 A = upk2(oA), Bv = upk2(oB);
            *(float2*)(Out + cbase + (l0 + r) * 1024 + 2 * lane)
                = make_float2((A.x + A.y) * g, (Bv.x + Bv.y) * g);
        }
        __syncwarp();
    }
}

extern "C" void kernel_launch(void* const* d_in, const int* in_sizes, int n_in,
                              void* d_out, int out_size)
{
    const float* Q     = (const float*)d_in[0];
    const float* K     = (const float*)d_in[1];
    const float* V     = (const float*)d_in[2];
    const float* delta = (const float*)d_in[3];
    float* Out = (float*)d_out;

    kv_kernel<<<512, 128>>>(K, V, delta);
    out_kernel<<<dim3(128, 3), 128>>>(Q, Out, delta);
}